// round 3
// baseline (speedup 1.0000x reference)
#include <cuda_runtime.h>
#include <math.h>

#define NB 256
#define NC 64
#define NL 512
#define NLABS 10
#define EMBD 256
#define CINA 82
#define PT 37056
#define O_BH 16384
#define O_WL 16448
#define O_BL 20544
#define O_WS 20608
#define O_BS 36992
#define PIF 3.14159274101257324f

__device__ float g_yemb[NB * EMBD];
__device__ float g_p[(size_t)NB * PT];
__device__ float g_x[(size_t)NB * NC * NL];
__device__ float g_xs[(size_t)NB * NC * NL];
__device__ float g_d1[(size_t)NB * NC * NL];
__device__ float g_xf[(size_t)NB * 4 * NC * NL];
__device__ float g_part[2048];

__device__ __forceinline__ float lrelu(float v) { return v > 0.f ? v : 0.2f * v; }

#define FMA2(d, a, b, c) asm("fma.rn.f32x2 %0, %1, %2, %3;" : "=l"(d) : "l"(a), "l"(b), "l"(c))
#define PACKDUP(d, f) { unsigned int _u = __float_as_uint(f); asm("mov.b64 %0, {%1, %2};" : "=l"(d) : "r"(_u), "r"(_u)); }
#define UNPK(lo, hi, v) { unsigned int _a, _b; asm("mov.b64 {%0, %1}, %2;" : "=r"(_a), "=r"(_b) : "l"(v)); lo = __uint_as_float(_a); hi = __uint_as_float(_b); }

// ---------------- yemb = normalize(fc_w[:,y] + fc_b) ----------------
__global__ void k_yemb(const float* __restrict__ fc_w, const float* __restrict__ fc_b,
                       const int* __restrict__ y) {
    int b = blockIdx.x, e = threadIdx.x;
    __shared__ float red[8];
    int lab = y[b];
    float v = fc_w[e * NLABS + lab] + fc_b[e];
    float ss = v * v;
#pragma unroll
    for (int o = 16; o; o >>= 1) ss += __shfl_xor_sync(0xffffffffu, ss, o);
    if ((e & 31) == 0) red[e >> 5] = ss;
    __syncthreads();
    if (e < 8) {
        float t = red[e];
#pragma unroll
        for (int o = 4; o; o >>= 1) t += __shfl_xor_sync(0xffu, t, o, 8);
        if (e == 0) red[0] = t;
    }
    __syncthreads();
    float nrm = fmaxf(sqrtf(red[0]), 1e-12f);
    g_yemb[b * EMBD + e] = v / nrm;
}

// ---------------- p = yemb @ hyper_w^T + hyper_b ----------------
__global__ void k_pgemm(const float* __restrict__ hw, const float* __restrict__ hb) {
    __shared__ float ys[64 * 65];
    __shared__ float ws[64 * 65];
    int j0 = blockIdx.x * 64, b0 = blockIdx.y * 64, tid = threadIdx.x;
    int jb = (tid & 15) * 4, bb = (tid >> 4) * 4;
    float acc[4][4];
#pragma unroll
    for (int v = 0; v < 4; v++)
#pragma unroll
        for (int u = 0; u < 4; u++) acc[v][u] = 0.f;
    for (int e0 = 0; e0 < EMBD; e0 += 64) {
        __syncthreads();
        for (int idx = tid; idx < 4096; idx += 256) {
            int r = idx >> 6, e = idx & 63;
            ys[r * 65 + e] = g_yemb[(b0 + r) * EMBD + e0 + e];
            ws[r * 65 + e] = hw[(size_t)(j0 + r) * EMBD + e0 + e];
        }
        __syncthreads();
#pragma unroll 4
        for (int e = 0; e < 64; e++) {
            float yv[4], wv[4];
#pragma unroll
            for (int v = 0; v < 4; v++) yv[v] = ys[(bb + v) * 65 + e];
#pragma unroll
            for (int u = 0; u < 4; u++) wv[u] = ws[(jb + u) * 65 + e];
#pragma unroll
            for (int v = 0; v < 4; v++)
#pragma unroll
                for (int u = 0; u < 4; u++) acc[v][u] = fmaf(yv[v], wv[u], acc[v][u]);
        }
    }
#pragma unroll
    for (int v = 0; v < 4; v++)
#pragma unroll
        for (int u = 0; u < 4; u++)
            g_p[(size_t)(b0 + bb + v) * PT + j0 + jb + u] = acc[v][u] + hb[j0 + jb + u];
}

// ---------------- x_cat = concat(codes, posenc) into g_xf scratch ----------------
__global__ void k_build(const float* __restrict__ codes) {
    int ci = blockIdx.x, b = blockIdx.y, l = threadIdx.x;
    float v;
    if (ci < NC) {
        v = codes[((size_t)b * NC + ci) * NL + l];
    } else {
        int f = ci - NC;
        int fe = (f < 9) ? f : f - 9;
        float ang = (PIF / (float)(1 << fe)) * (float)l;
        v = (f < 9) ? sinf(ang) : cosf(ang);
    }
    g_xf[((size_t)b * CINA + ci) * NL + l] = v;
}

// ---------------- xs = 1x1 conv (in_ws) on x_cat ----------------
__global__ void k_sel1x1(const float* __restrict__ ws) {
    __shared__ float xt[CINA * 64];
    __shared__ float wt[CINA * 64];
    int b = blockIdx.y, l0 = blockIdx.x * 64, tid = threadIdx.x;
    int l = tid & 63, cg = tid >> 6;
    for (int idx = tid; idx < CINA * 64; idx += 256) {
        int ci = idx >> 6;
        xt[idx] = g_xf[((size_t)b * CINA + ci) * NL + l0 + (idx & 63)];
        wt[ci * 64 + (idx & 63)] = ws[(idx & 63) * CINA + ci];
    }
    __syncthreads();
    float acc[16];
#pragma unroll
    for (int r = 0; r < 16; r++) acc[r] = 0.f;
    for (int ci = 0; ci < CINA; ci++) {
        float a = xt[ci * 64 + l];
        const float* wr = &wt[ci * 64 + cg * 16];
#pragma unroll
        for (int r = 0; r < 16; r++) acc[r] = fmaf(wr[r], a, acc[r]);
    }
#pragma unroll
    for (int r = 0; r < 16; r++)
        g_xs[((size_t)b * NC + cg * 16 + r) * NL + l0 + l] = acc[r];
}

// ---------------- generic k3 conv (leaky on input), optional residual base ----------------
__global__ void k_conv3(const float* __restrict__ xin, int cin,
                        const float* __restrict__ w, const float* __restrict__ bias,
                        const float* __restrict__ base, float* __restrict__ out) {
    __shared__ float xt[32 * 66];
    __shared__ float wt[3][32 * 64];
    int b = blockIdx.y, l0 = blockIdx.x * 64, tid = threadIdx.x;
    int l = tid & 63, cg = tid >> 6;
    float acc[16];
#pragma unroll
    for (int r = 0; r < 16; r++) acc[r] = 0.f;
    for (int ci0 = 0; ci0 < cin; ci0 += 32) {
        int cs = min(32, cin - ci0);
        __syncthreads();
        for (int idx = tid; idx < cs * 66; idx += 256) {
            int ci = idx / 66, j = idx - ci * 66;
            int pos = l0 + j - 1;
            float v = (pos >= 0 && pos < NL) ? xin[((size_t)b * cin + ci0 + ci) * NL + pos] : 0.f;
            xt[ci * 66 + j] = lrelu(v);
        }
        for (int idx = tid; idx < cs * 64; idx += 256) {
            int co = idx & 63, ci = idx >> 6;
            const float* wp = w + ((size_t)co * cin + ci0 + ci) * 3;
            wt[0][ci * 64 + co] = wp[0];
            wt[1][ci * 64 + co] = wp[1];
            wt[2][ci * 64 + co] = wp[2];
        }
        __syncthreads();
        for (int ci = 0; ci < cs; ci++) {
            float a0 = xt[ci * 66 + l], a1 = xt[ci * 66 + l + 1], a2 = xt[ci * 66 + l + 2];
            const float* w0r = &wt[0][ci * 64 + cg * 16];
            const float* w1r = &wt[1][ci * 64 + cg * 16];
            const float* w2r = &wt[2][ci * 64 + cg * 16];
#pragma unroll
            for (int r = 0; r < 16; r++)
                acc[r] += w0r[r] * a0 + w1r[r] * a1 + w2r[r] * a2;
        }
    }
#pragma unroll
    for (int r = 0; r < 16; r++) {
        int co = cg * 16 + r;
        size_t o = ((size_t)b * NC + co) * NL + l0 + l;
        float v = acc[r] + bias[co];
        out[o] = base ? base[o] + 0.1f * v : v;
    }
}

// ---------------- instance-norm + sobel + sin -> g_xf (B,256,512) ----------------
__global__ void k_sobel() {
    __shared__ float xs[512];
    __shared__ float red[32];
    int c = blockIdx.x, b = blockIdx.y, t = threadIdx.x;
    float v = g_x[((size_t)b * NC + c) * NL + t];
    float s = v, q = v * v;
#pragma unroll
    for (int o = 16; o; o >>= 1) {
        s += __shfl_xor_sync(0xffffffffu, s, o);
        q += __shfl_xor_sync(0xffffffffu, q, o);
    }
    if ((t & 31) == 0) { red[t >> 5] = s; red[16 + (t >> 5)] = q; }
    __syncthreads();
    if (t < 16) {
        float s2 = red[t], q2 = red[16 + t];
#pragma unroll
        for (int o = 8; o; o >>= 1) {
            s2 += __shfl_xor_sync(0xffffu, s2, o, 16);
            q2 += __shfl_xor_sync(0xffffu, q2, o, 16);
        }
        if (t == 0) { red[0] = s2; red[1] = q2; }
    }
    __syncthreads();
    float mean = red[0] * (1.f / 512.f);
    float var = red[1] * (1.f / 512.f) - mean * mean;
    float xn = (v - mean) * rsqrtf(var + 1e-5f);
    xs[t] = xn;
    __syncthreads();
    int d0 = t >> 6, d1 = (t >> 3) & 7, d2 = t & 7;
    const float dd[3] = {-1.f, 0.f, 1.f}, sb[3] = {1.f, 2.f, 1.f};
    float gx = 0.f, gy = 0.f, gz = 0.f;
#pragma unroll
    for (int a = 0; a < 3; a++) {
        int p0 = d0 + a - 1;
        if ((unsigned)p0 > 7u) continue;
#pragma unroll
        for (int e = 0; e < 3; e++) {
            int p1 = d1 + e - 1;
            if ((unsigned)p1 > 7u) continue;
#pragma unroll
            for (int f = 0; f < 3; f++) {
                int p2 = d2 + f - 1;
                if ((unsigned)p2 > 7u) continue;
                float val = xs[(p0 << 6) + (p1 << 3) + p2];
                gx += dd[a] * sb[e] * sb[f] * val;
                gy += sb[a] * dd[e] * sb[f] * val;
                gz += sb[a] * sb[e] * dd[f] * val;
            }
        }
    }
    size_t base = ((size_t)b * 4 * NC + c) * NL + t;
    g_xf[base] = xn;
    g_xf[base + (size_t)NC * NL] = __sinf(gx);
    g_xf[base + (size_t)2 * NC * NL] = __sinf(gy);
    g_xf[base + (size_t)3 * NC * NL] = __sinf(gz);
}

// ---------------- fused dyna + residual: x += leak * dyna(xf, p) ----------------
__global__ void __launch_bounds__(256) k_dyna(const float* __restrict__ leak_ptr) {
    extern __shared__ float sm[];
    int b = blockIdx.y, s0 = blockIdx.x * 128, tid = threadIdx.x;
    int sb = (tid & 15) * 8, cb = (tid >> 4) * 4;
    const float* pb = g_p + (size_t)b * PT;
    const float* xfb = g_xf + (size_t)b * 4 * NC * NL;
    unsigned long long ah2[4][4], ao2[4][4];
#pragma unroll
    for (int r = 0; r < 4; r++)
#pragma unroll
        for (int q = 0; q < 4; q++) { ah2[r][q] = 0ull; ao2[r][q] = 0ull; }
    float* xch = sm;          // 4096
    float* whs = sm + 4096;   // 32*68 = 2176
    float* wss = sm + 6272;   // 2176
    for (int ch = 0; ch < 8; ch++) {
        int ci0 = ch * 32;
        if (ch) __syncthreads();
        for (int idx = tid; idx < 4096; idx += 256)
            xch[idx] = xfb[(size_t)(ci0 + (idx >> 7)) * NL + s0 + (idx & 127)];
        for (int idx = tid; idx < 2048; idx += 256) {
            int ci = idx & 31, co = idx >> 5;
            whs[ci * 68 + co] = pb[co * 256 + ci0 + ci];
            wss[ci * 68 + co] = pb[O_WS + co * 256 + ci0 + ci];
        }
        __syncthreads();
#pragma unroll 4
        for (int ci = 0; ci < 32; ci++) {
            ulonglong2 xa = *(const ulonglong2*)(xch + ci * 128 + sb);
            ulonglong2 xb = *(const ulonglong2*)(xch + ci * 128 + sb + 4);
            unsigned long long xp[4] = {xa.x, xa.y, xb.x, xb.y};
            float4 wh4 = *(const float4*)(whs + ci * 68 + cb);
            float4 ws4 = *(const float4*)(wss + ci * 68 + cb);
            float whf[4] = {wh4.x, wh4.y, wh4.z, wh4.w};
            float wsf[4] = {ws4.x, ws4.y, ws4.z, ws4.w};
#pragma unroll
            for (int r = 0; r < 4; r++) {
                unsigned long long w2, v2;
                PACKDUP(w2, whf[r]);
                PACKDUP(v2, wsf[r]);
#pragma unroll
                for (int q = 0; q < 4; q++) {
                    FMA2(ah2[r][q], w2, xp[q], ah2[r][q]);
                    FMA2(ao2[r][q], v2, xp[q], ao2[r][q]);
                }
            }
        }
    }
    __syncthreads();
    // phase 2: h = leaky(ah + bh) into smem, then wl GEMM
    float* ht = sm;          // 8192
    float* wls = sm + 8192;  // 64*68 = 4352
#pragma unroll
    for (int r = 0; r < 4; r++) {
        float bh = pb[O_BH + cb + r];
#pragma unroll
        for (int q = 0; q < 4; q++) {
            float lo, hi;
            UNPK(lo, hi, ah2[r][q]);
            ht[(cb + r) * 128 + sb + 2 * q] = lrelu(lo + bh);
            ht[(cb + r) * 128 + sb + 2 * q + 1] = lrelu(hi + bh);
        }
    }
    for (int idx = tid; idx < 4096; idx += 256)
        wls[(idx & 63) * 68 + (idx >> 6)] = pb[O_WL + (idx >> 6) * 64 + (idx & 63)];
    unsigned long long al2[4][4];
#pragma unroll
    for (int r = 0; r < 4; r++)
#pragma unroll
        for (int q = 0; q < 4; q++) al2[r][q] = 0ull;
    __syncthreads();
#pragma unroll 4
    for (int hh = 0; hh < 64; hh++) {
        ulonglong2 ha = *(const ulonglong2*)(ht + hh * 128 + sb);
        ulonglong2 hb2 = *(const ulonglong2*)(ht + hh * 128 + sb + 4);
        unsigned long long hp[4] = {ha.x, ha.y, hb2.x, hb2.y};
        float4 wl4 = *(const float4*)(wls + hh * 68 + cb);
        float wlf[4] = {wl4.x, wl4.y, wl4.z, wl4.w};
#pragma unroll
        for (int r = 0; r < 4; r++) {
            unsigned long long w2;
            PACKDUP(w2, wlf[r]);
#pragma unroll
            for (int q = 0; q < 4; q++) FMA2(al2[r][q], w2, hp[q], al2[r][q]);
        }
    }
    float leak = fminf(fmaxf(*leak_ptr, 0.001f), 1000.f);
#pragma unroll
    for (int r = 0; r < 4; r++) {
        int co = cb + r;
        float bs = pb[O_BS + co], bl = pb[O_BL + co];
        float* xp_ = g_x + ((size_t)b * NC + co) * NL + s0 + sb;
        float4 o0 = *(float4*)xp_;
        float4 o1 = *(float4*)(xp_ + 4);
        float ov[8] = {o0.x, o0.y, o0.z, o0.w, o1.x, o1.y, o1.z, o1.w};
#pragma unroll
        for (int q = 0; q < 4; q++) {
            float so, sh, dl, dh;
            UNPK(so, sh, ao2[r][q]);
            UNPK(dl, dh, al2[r][q]);
            ov[2 * q] += leak * (so + bs + 0.1f * (dl + bl));
            ov[2 * q + 1] += leak * (sh + bs + 0.1f * (dh + bl));
        }
        *(float4*)xp_ = make_float4(ov[0], ov[1], ov[2], ov[3]);
        *(float4*)(xp_ + 4) = make_float4(ov[4], ov[5], ov[6], ov[7]);
    }
}

// ---------------- CE loss partials ----------------
__global__ void k_loss(const float* __restrict__ codes) {
    __shared__ float xt[64 * 64];
    __shared__ float ct[64 * 64];
    __shared__ float red[8];
    int b = blockIdx.y, l0 = blockIdx.x * 64, tid = threadIdx.x;
    for (int idx = tid; idx < 4096; idx += 256) {
        int c = idx >> 6, lw = idx & 63;
        xt[idx] = g_xs[((size_t)b * NC + c) * NL + l0 + lw];
        ct[idx] = codes[((size_t)b * NC + c) * NL + l0 + lw];
    }
    __syncthreads();
    float mysum = 0.f;
    if (tid < 64) {
        int l = tid;
        float m = xt[l];
        for (int c = 1; c < 64; c++) m = fmaxf(m, xt[c * 64 + l]);
        float se = 0.f;
        for (int c = 0; c < 64; c++) se += expf(xt[c * 64 + l] - m);
        float cm = ct[l];
        int ci = 0;
        for (int c = 1; c < 64; c++) {
            float v = ct[c * 64 + l];
            if (v > cm) { cm = v; ci = c; }
        }
        mysum = -(xt[ci * 64 + l] - m - logf(se));
    }
#pragma unroll
    for (int o = 16; o; o >>= 1) mysum += __shfl_xor_sync(0xffffffffu, mysum, o);
    if ((tid & 31) == 0) red[tid >> 5] = mysum;
    __syncthreads();
    if (tid < 8) {
        float t = red[tid];
#pragma unroll
        for (int o = 4; o; o >>= 1) t += __shfl_xor_sync(0xffu, t, o, 8);
        if (tid == 0) g_part[b * 8 + blockIdx.x] = t;
    }
}

__global__ void k_loss_final(float* __restrict__ out) {
    __shared__ float red[16];
    int t = threadIdx.x;
    float s = g_part[t] + g_part[t + 512] + g_part[t + 1024] + g_part[t + 1536];
#pragma unroll
    for (int o = 16; o; o >>= 1) s += __shfl_xor_sync(0xffffffffu, s, o);
    if ((t & 31) == 0) red[t >> 5] = s;
    __syncthreads();
    if (t < 16) {
        float v = red[t];
#pragma unroll
        for (int o = 8; o; o >>= 1) v += __shfl_xor_sync(0xffffu, v, o, 16);
        if (t == 0) out[131072] = v * (1.f / 131072.f);
    }
}

// ---------------- lat head: two 1x1 res blocks ----------------
__global__ void k_lat(const float* __restrict__ w0, const float* __restrict__ b0,
                      const float* __restrict__ w1, const float* __restrict__ b1,
                      const float* __restrict__ l2w0, const float* __restrict__ l2b0,
                      const float* __restrict__ l2w1, const float* __restrict__ l2b1,
                      const float* __restrict__ l2ws, float* __restrict__ out) {
    extern __shared__ float sm[];
    float* xt = sm;          // 4096
    float* ht = sm + 4096;   // 4096
    float* wb = sm + 8192;   // 4096
    float* rp = sm;          // reuse xt region after done (512)
    int b = blockIdx.y, l0 = blockIdx.x * 64, tid = threadIdx.x;
    int l = tid & 63, cg = tid >> 6;
    for (int idx = tid; idx < 4096; idx += 256) {
        int c = idx >> 6, ll = idx & 63;
        xt[idx] = g_xs[((size_t)b * NC + c) * NL + l0 + ll];
        wb[c * 64 + ll] = w0[ll * 64 + c];  // wb[ci][co]
    }
    __syncthreads();
    float acc[16];
#pragma unroll
    for (int r = 0; r < 16; r++) acc[r] = 0.f;
    for (int ci = 0; ci < 64; ci++) {
        float a = lrelu(xt[ci * 64 + l]);
        const float* wr = &wb[ci * 64 + cg * 16];
#pragma unroll
        for (int r = 0; r < 16; r++) acc[r] = fmaf(wr[r], a, acc[r]);
    }
#pragma unroll
    for (int r = 0; r < 16; r++) ht[(cg * 16 + r) * 64 + l] = acc[r] + b0[cg * 16 + r];
    __syncthreads();
    for (int idx = tid; idx < 4096; idx += 256)
        wb[(idx >> 6) * 64 + (idx & 63)] = w1[(idx & 63) * 64 + (idx >> 6)];
    __syncthreads();
#pragma unroll
    for (int r = 0; r < 16; r++) acc[r] = 0.f;
    for (int ci = 0; ci < 64; ci++) {
        float a = lrelu(ht[ci * 64 + l]);
        const float* wr = &wb[ci * 64 + cg * 16];
#pragma unroll
        for (int r = 0; r < 16; r++) acc[r] = fmaf(wr[r], a, acc[r]);
    }
    float lat1v[16];
#pragma unroll
    for (int r = 0; r < 16; r++)
        lat1v[r] = xt[(cg * 16 + r) * 64 + l] + 0.1f * (acc[r] + b1[cg * 16 + r]);
    __syncthreads();
#pragma unroll
    for (int r = 0; r < 16; r++) ht[(cg * 16 + r) * 64 + l] = lat1v[r];
    __syncthreads();
    float s1 = 0.f, s2 = 0.f;
#pragma unroll
    for (int k = 0; k < 16; k++) {
        int ci = cg * 16 + k;
        float v = ht[ci * 64 + l];
        s1 += l2ws[ci] * v;
        s2 += l2w0[ci] * lrelu(v);
    }
    rp[cg * 64 + l] = s1;
    rp[256 + cg * 64 + l] = s2;
    __syncthreads();
    if (tid < 64) {
        float S1 = rp[tid] + rp[64 + tid] + rp[128 + tid] + rp[192 + tid];
        float S2 = rp[256 + tid] + rp[320 + tid] + rp[384 + tid] + rp[448 + tid];
        float dd = l2b0[0] + S2;
        out[(size_t)b * NL + l0 + tid] = S1 + 0.1f * (l2b1[0] + l2w1[0] * lrelu(dd));
    }
}

extern "C" void kernel_launch(void* const* d_in, const int* in_sizes, int n_in,
                              void* d_out, int out_size) {
    const float* codes  = (const float*)d_in[0];
    const int*   y      = (const int*)d_in[1];
    const float* fc_w   = (const float*)d_in[2];
    const float* fc_b   = (const float*)d_in[3];
    const float* in_w0  = (const float*)d_in[4];
    const float* in_b0  = (const float*)d_in[5];
    const float* in_w1  = (const float*)d_in[6];
    const float* in_b1  = (const float*)d_in[7];
    const float* in_ws  = (const float*)d_in[8];
    const float* leak   = (const float*)d_in[9];
    const float* hyper_w = (const float*)d_in[10];
    const float* hyper_b = (const float*)d_in[11];
    const float* out_w0 = (const float*)d_in[12];
    const float* out_b0 = (const float*)d_in[13];
    const float* out_w1 = (const float*)d_in[14];
    const float* out_b1 = (const float*)d_in[15];
    const float* l1_w0  = (const float*)d_in[16];
    const float* l1_b0  = (const float*)d_in[17];
    const float* l1_w1  = (const float*)d_in[18];
    const float* l1_b1  = (const float*)d_in[19];
    const float* l2_w0  = (const float*)d_in[20];
    const float* l2_b0  = (const float*)d_in[21];
    const float* l2_w1  = (const float*)d_in[22];
    const float* l2_b1  = (const float*)d_in[23];
    const float* l2_ws  = (const float*)d_in[24];
    float* out = (float*)d_out;

    float *px, *pxs, *pd1, *pxf;
    cudaGetSymbolAddress((void**)&px, g_x);
    cudaGetSymbolAddress((void**)&pxs, g_xs);
    cudaGetSymbolAddress((void**)&pd1, g_d1);
    cudaGetSymbolAddress((void**)&pxf, g_xf);

    cudaFuncSetAttribute(k_dyna, cudaFuncAttributeMaxDynamicSharedMemorySize, 50176);
    cudaFuncSetAttribute(k_lat, cudaFuncAttributeMaxDynamicSharedMemorySize, 49152);

    k_yemb<<<NB, 256>>>(fc_w, fc_b, y);
    k_pgemm<<<dim3(PT / 64, NB / 64), 256>>>(hyper_w, hyper_b);
    k_build<<<dim3(CINA, NB), NL>>>(codes);
    k_sel1x1<<<dim3(8, NB), 256>>>(in_ws);
    k_conv3<<<dim3(8, NB), 256>>>(pxf, CINA, in_w0, in_b0, nullptr, pd1);
    k_conv3<<<dim3(8, NB), 256>>>(pd1, NC, in_w1, in_b1, pxs, px);
    for (int it = 0; it < 8; it++) {
        k_sobel<<<dim3(NC, NB), NL>>>();
        k_dyna<<<dim3(4, NB), 256, 50176>>>(leak);
    }
    k_conv3<<<dim3(8, NB), 256>>>(px, NC, out_w0, out_b0, nullptr, pd1);
    k_conv3<<<dim3(8, NB), 256>>>(pd1, NC, out_w1, out_b1, px, pxs);
    k_loss<<<dim3(8, NB), 256>>>(codes);
    k_loss_final<<<1, 512>>>(out);
    k_lat<<<dim3(8, NB), 256, 49152>>>(l1_w0, l1_b0, l1_w1, l1_b1,
                                       l2_w0, l2_b0, l2_w1, l2_b1, l2_ws, out);
}